// round 4
// baseline (speedup 1.0000x reference)
#include <cuda_runtime.h>
#include <cuda_fp16.h>
#include <cstdint>

// ---------------------------------------------------------------------------
// QLoRA 4-bit: y = x @ (dequant(W)^T + 2 * W_a @ W_b)
//   1) round_xh:     x -> fp16 copy (d_Xh)
//   2) build_weff_h: NF4 dequant + LoRA fold -> fp16 W_eff[OUT][IN]
//   3) qgemm_h:      fp16 mma.sync m16n8k16 GEMM, f32 accum.
//      CTA 256x128, BK=32, 512 thr (16 warps, warp tile 64x32),
//      4-stage cp.async, ldmatrix.x4 fragment loads.
// (tcgen05 is unusable here: harness compiles PTX for compute_103 w/o 'a'.)
// ---------------------------------------------------------------------------

namespace {
constexpr int D_IN  = 4096;
constexpr int D_OUT = 4096;
constexpr int M_TOK = 8192;
constexpr int RNK   = 16;

constexpr int BM = 256, BN = 128, BK = 32;     // BK halves = 64 bytes
constexpr int KP = 40;                          // padded row, halves (80 B)
constexpr int STAGES = 4;
constexpr int NT = D_IN / BK;                   // 128
constexpr int A_ST_BYTES = BM * KP * 2;         // 20480
constexpr int B_ST_BYTES = BN * KP * 2;         // 10240
constexpr int STAGE_BYTES = A_ST_BYTES + B_ST_BYTES;   // 30720
constexpr int SMEM_DYN = STAGES * STAGE_BYTES;         // 122880
constexpr int NTHREADS = 512;
}

// scratch (allocation-free rule: __device__ globals)
__device__ __align__(16) __half d_Weff[(size_t)D_OUT * D_IN];  // 32 MB
__device__ __align__(16) __half d_Xh[(size_t)M_TOK * D_IN];    // 64 MB

__constant__ float c_nf4[16] = {
    -1.0f, -0.6961928009986877f, -0.5250730514526367f, -0.39491748809814453f,
    -0.28444138169288635f, -0.18477343022823334f, -0.09105003625154495f, 0.0f,
    0.07958029955625534f, 0.16093020141124725f, 0.24611230194568634f,
    0.33791524171829224f, 0.44070982933044434f, 0.5626170039176941f,
    0.7229568362236023f, 1.0f};

__device__ __forceinline__ uint32_t smem_u32(const void* p) {
    uint32_t a;
    asm("{ .reg .u64 t; cvta.to.shared.u64 t, %1; cvt.u32.u64 %0, t; }" : "=r"(a) : "l"(p));
    return a;
}
__device__ __forceinline__ void cp_async16(uint32_t saddr, const void* gaddr) {
    asm volatile("cp.async.cg.shared.global [%0], [%1], 16;\n" :: "r"(saddr), "l"(gaddr));
}
__device__ __forceinline__ void ldsm_x4(uint32_t& r0, uint32_t& r1, uint32_t& r2,
                                        uint32_t& r3, uint32_t addr) {
    asm volatile("ldmatrix.sync.aligned.m8n8.x4.shared.b16 {%0,%1,%2,%3}, [%4];"
                 : "=r"(r0), "=r"(r1), "=r"(r2), "=r"(r3) : "r"(addr));
}
__device__ __forceinline__ void mma16816(float* d, const uint32_t* a, const uint32_t* b) {
    asm volatile(
        "mma.sync.aligned.m16n8k16.row.col.f32.f16.f16.f32 "
        "{%0,%1,%2,%3}, {%4,%5,%6,%7}, {%8,%9}, {%0,%1,%2,%3};\n"
        : "+f"(d[0]), "+f"(d[1]), "+f"(d[2]), "+f"(d[3])
        : "r"(a[0]), "r"(a[1]), "r"(a[2]), "r"(a[3]), "r"(b[0]), "r"(b[1]));
}

// ---------------------------------------------------------------------------
__global__ void round_xh_kernel(const float4* __restrict__ x, uint2* __restrict__ xh, int n4) {
    int i = blockIdx.x * blockDim.x + threadIdx.x;
    int stride = gridDim.x * blockDim.x;
    for (; i < n4; i += stride) {
        float4 v = x[i];
        __half2 lo = __floats2half2_rn(v.x, v.y);
        __half2 hi = __floats2half2_rn(v.z, v.w);
        xh[i] = make_uint2(*reinterpret_cast<uint32_t*>(&lo),
                           *reinterpret_cast<uint32_t*>(&hi));
    }
}

// W_eff[n][k] = nf4[codes[n][k]]*absmax[n][k/64] + 2*sum_r Wa[k][r]*Wb[r][n]
__global__ void build_weff_kernel(const int* __restrict__ codes,
                                  const float* __restrict__ absmax,
                                  const float* __restrict__ Wa,
                                  const float* __restrict__ Wb) {
    const int n = blockIdx.x;
    float wb[RNK];
#pragma unroll
    for (int r = 0; r < RNK; r++) wb[r] = __ldg(&Wb[r * D_OUT + n]);

    const int*   crow = codes  + (size_t)n * D_IN;
    const float* am   = absmax + (size_t)n * (D_IN / 64);
    __half*      orow = d_Weff + (size_t)n * D_IN;

    for (int k = threadIdx.x; k < D_IN; k += blockDim.x) {
        float w = c_nf4[crow[k] & 15] * am[k >> 6];
        const float4* wa = reinterpret_cast<const float4*>(Wa + (size_t)k * RNK);
        float4 a0 = wa[0], a1 = wa[1], a2 = wa[2], a3 = wa[3];
        float l = a0.x * wb[0]  + a0.y * wb[1]  + a0.z * wb[2]  + a0.w * wb[3]
                + a1.x * wb[4]  + a1.y * wb[5]  + a1.z * wb[6]  + a1.w * wb[7]
                + a2.x * wb[8]  + a2.y * wb[9]  + a2.z * wb[10] + a2.w * wb[11]
                + a3.x * wb[12] + a3.y * wb[13] + a3.z * wb[14] + a3.w * wb[15];
        orow[k] = __float2half_rn(w + 2.0f * l);   // SCALE = 2
    }
}

// ---------------------------------------------------------------------------
__global__ __launch_bounds__(NTHREADS, 1)
void qgemm_h(const __half* __restrict__ A, float* __restrict__ C) {
    extern __shared__ char smem[];
    const uint32_t sb = smem_u32(smem);

    const int tid  = threadIdx.x, lane = tid & 31, warp = tid >> 5;
    const int warpM = warp & 3;          // 4 slabs of 64 rows
    const int warpN = warp >> 2;         // 4 slabs of 32 cols
    const int gid = lane >> 2, tig = lane & 3;

    const int mBase = blockIdx.y * BM;
    const int nBase = blockIdx.x * BN;

    const __half* Abase = A      + (size_t)mBase * D_IN;
    const __half* Bbase = d_Weff + (size_t)nBase * D_IN;

    // per-thread cp.async chunk map (3 x 16B per stage)
    const int ia0 = tid, ia1 = tid + 512;   // A chunks (1024 total)
    const int ib0 = tid;                    // B chunks (512 total)

    auto load_stage = [&](int s, int kt) {
        const uint32_t st = sb + s * STAGE_BYTES;
        const char* Ag = (const char*)(Abase) + (size_t)kt * 64;
        const char* Bg = (const char*)(Bbase) + (size_t)kt * 64;
        {
            int row = ia0 >> 2, seg = (ia0 & 3) << 4;
            cp_async16(st + row * (KP * 2) + seg, Ag + (size_t)row * (D_IN * 2) + seg);
        }
        {
            int row = ia1 >> 2, seg = (ia1 & 3) << 4;
            cp_async16(st + row * (KP * 2) + seg, Ag + (size_t)row * (D_IN * 2) + seg);
        }
        {
            int row = ib0 >> 2, seg = (ib0 & 3) << 4;
            cp_async16(st + A_ST_BYTES + row * (KP * 2) + seg,
                       Bg + (size_t)row * (D_IN * 2) + seg);
        }
    };

    float acc[4][4][4];
#pragma unroll
    for (int i = 0; i < 4; i++)
#pragma unroll
        for (int j = 0; j < 4; j++)
#pragma unroll
            for (int v = 0; v < 4; v++) acc[i][j][v] = 0.f;

    // prologue: stages 0..STAGES-2
#pragma unroll
    for (int s = 0; s < STAGES - 1; s++) {
        load_stage(s, s);
        asm volatile("cp.async.commit_group;\n");
    }

    // precomputed ldmatrix lane offsets
    const uint32_t aRow = (lane & 15);
    const uint32_t aCol = ((lane >> 4) & 1) << 4;             // bytes
    const uint32_t bRow = (lane & 7) + (((lane >> 4) & 1) << 3);
    const uint32_t bCol = ((lane >> 3) & 1) << 4;             // bytes

    for (int kt = 0; kt < NT; kt++) {
        asm volatile("cp.async.wait_group %0;\n" :: "n"(STAGES - 2));
        __syncthreads();
        const int s = kt & (STAGES - 1);
        const uint32_t Ast = sb + s * STAGE_BYTES;
        const uint32_t Bst = Ast + A_ST_BYTES;

#pragma unroll
        for (int kh = 0; kh < 2; kh++) {           // two k16 halves of BK=32
            uint32_t a[4][4];
#pragma unroll
            for (int mi = 0; mi < 4; mi++) {
                uint32_t addr = Ast + (warpM * 64 + mi * 16 + aRow) * (KP * 2)
                              + kh * 32 + aCol;
                ldsm_x4(a[mi][0], a[mi][1], a[mi][2], a[mi][3], addr);
            }
            uint32_t b[4][2];
#pragma unroll
            for (int nb = 0; nb < 2; nb++) {
                uint32_t r0, r1, r2, r3;
                uint32_t addr = Bst + (warpN * 32 + nb * 16 + bRow) * (KP * 2)
                              + kh * 32 + bCol;
                ldsm_x4(r0, r1, r2, r3, addr);
                b[2 * nb][0] = r0; b[2 * nb][1] = r1;
                b[2 * nb + 1][0] = r2; b[2 * nb + 1][1] = r3;
            }
#pragma unroll
            for (int mi = 0; mi < 4; mi++)
#pragma unroll
                for (int ni = 0; ni < 4; ni++)
                    mma16816(acc[mi][ni], a[mi], b[ni]);
        }

        if (kt + STAGES - 1 < NT)
            load_stage((kt + STAGES - 1) & (STAGES - 1), kt + STAGES - 1);
        asm volatile("cp.async.commit_group;\n");
    }

    // epilogue: float2 stores
#pragma unroll
    for (int mi = 0; mi < 4; mi++) {
        const int row0 = mBase + warpM * 64 + mi * 16 + gid;
#pragma unroll
        for (int ni = 0; ni < 4; ni++) {
            const int col = nBase + warpN * 32 + ni * 8 + tig * 2;
            *reinterpret_cast<float2*>(C + (size_t)row0 * D_OUT + col) =
                make_float2(acc[mi][ni][0], acc[mi][ni][1]);
            *reinterpret_cast<float2*>(C + (size_t)(row0 + 8) * D_OUT + col) =
                make_float2(acc[mi][ni][2], acc[mi][ni][3]);
        }
    }
}

// ---------------------------------------------------------------------------
extern "C" void kernel_launch(void* const* d_in, const int* in_sizes, int n_in,
                              void* d_out, int out_size) {
    const float* x      = (const float*)d_in[0];
    const int*   codes  = (const int*)  d_in[1];
    const float* absmax = (const float*)d_in[2];
    const float* Wa     = (const float*)d_in[3];
    const float* Wb     = (const float*)d_in[4];
    float* out = (float*)d_out;

    cudaFuncSetAttribute(qgemm_h, cudaFuncAttributeMaxDynamicSharedMemorySize, SMEM_DYN);

    round_xh_kernel<<<4096, 256>>>((const float4*)x, (uint2*)d_Xh,
                                   (int)((size_t)M_TOK * D_IN / 4));
    build_weff_kernel<<<D_OUT, 256>>>(codes, absmax, Wa, Wb);

    dim3 grid(D_OUT / BN, M_TOK / BM);   // (32, 32), n-fast for W_eff L2 reuse
    qgemm_h<<<grid, NTHREADS, SMEM_DYN>>>(d_Xh, out);
}